// round 11
// baseline (speedup 1.0000x reference)
#include <cuda_runtime.h>
#include <stdint.h>

// QLinearLayerSign via int8 mma.sync, v2 (ldmatrix + occupancy + 3-stage):
//   A[m,k] = (x>0) ? 1 : 0   (s8)
//   B[n,k] = (W>0) ? 1 : -1  (s8)
//   out[m,n] = (float) sum_k A*B   (s32 accum, exact)

#define BATCH 8192
#define INF   4096
#define OUTF  4096

#define BM 128
#define BN 128
#define BK 64                     // bytes of k per chunk
#define KCHUNKS (INF / BK)        // 64
#define RS 80                     // smem row stride (64 data + 16 pad, conflict-free)

#define STG_A  (BM * RS)          // 10240
#define STG_SZ (2 * STG_A)        // 20480 (A then B)
#define NSTG   3
#define SM_TOTAL (NSTG * STG_SZ)  // 61440

__device__ int8_t g_X8[(size_t)BATCH * INF];   // 32 MB
__device__ int8_t g_W8[(size_t)OUTF * INF];    // 16 MB

__device__ __forceinline__ uint32_t smem_u32(const void* p) {
    uint32_t a;
    asm("{ .reg .u64 t; cvta.to.shared.u64 t, %1; cvt.u32.u64 %0, t; }" : "=r"(a) : "l"(p));
    return a;
}
__device__ __forceinline__ void cp16(uint32_t dst, const void* src) {
    asm volatile("cp.async.cg.shared.global [%0], [%1], 16;" :: "r"(dst), "l"(src));
}
__device__ __forceinline__ void cp_commit() {
    asm volatile("cp.async.commit_group;" ::: "memory");
}
template <int N> __device__ __forceinline__ void cp_wait() {
    asm volatile("cp.async.wait_group %0;" :: "n"(N) : "memory");
}
__device__ __forceinline__ void ldm_x4(uint32_t* r, uint32_t addr) {
    asm volatile("ldmatrix.sync.aligned.m8n8.x4.shared.b16 {%0,%1,%2,%3}, [%4];"
                 : "=r"(r[0]), "=r"(r[1]), "=r"(r[2]), "=r"(r[3]) : "r"(addr));
}
__device__ __forceinline__ void imma(int* d, const uint32_t* a, const uint32_t* b) {
    asm volatile(
        "mma.sync.aligned.m16n8k32.row.col.s32.s8.s8.s32 "
        "{%0,%1,%2,%3}, {%4,%5,%6,%7}, {%8,%9}, {%0,%1,%2,%3};"
        : "+r"(d[0]), "+r"(d[1]), "+r"(d[2]), "+r"(d[3])
        : "r"(a[0]), "r"(a[1]), "r"(a[2]), "r"(a[3]), "r"(b[0]), "r"(b[1]));
}

// ---------------------------------------------------------------------------
// fp32 -> s8 conversion (16 elems/thread).
// ---------------------------------------------------------------------------
__global__ __launch_bounds__(256) void conv_x8_kernel(const float* __restrict__ x,
                                                      int8_t* __restrict__ d) {
    size_t base = ((size_t)blockIdx.x * 256 + threadIdx.x) * 16;
    uint32_t w[4];
    #pragma unroll
    for (int i = 0; i < 4; ++i) {
        float4 f = *reinterpret_cast<const float4*>(x + base + i * 4);
        w[i] = (f.x > 0.f ? 1u : 0u) | ((f.y > 0.f ? 1u : 0u) << 8) |
               ((f.z > 0.f ? 1u : 0u) << 16) | ((f.w > 0.f ? 1u : 0u) << 24);
    }
    *reinterpret_cast<uint4*>(d + base) = make_uint4(w[0], w[1], w[2], w[3]);
}
__global__ __launch_bounds__(256) void conv_w8_kernel(const float* __restrict__ x,
                                                      int8_t* __restrict__ d) {
    size_t base = ((size_t)blockIdx.x * 256 + threadIdx.x) * 16;
    uint32_t w[4];
    #pragma unroll
    for (int i = 0; i < 4; ++i) {
        float4 f = *reinterpret_cast<const float4*>(x + base + i * 4);
        w[i] = (f.x > 0.f ? 1u : 0xFFu) | ((f.y > 0.f ? 1u : 0xFFu) << 8) |
               ((f.z > 0.f ? 1u : 0xFFu) << 16) | ((f.w > 0.f ? 1u : 0xFFu) << 24);
    }
    *reinterpret_cast<uint4*>(d + base) = make_uint4(w[0], w[1], w[2], w[3]);
}

// ---------------------------------------------------------------------------
// IMMA v2: CTA 128x128, 8 warps, warp tile 32x64 (2 m16 x 8 n8), BK=64,
// ldmatrix fragment loads, 3-stage cp.async pipeline, 2 CTAs/SM.
// ---------------------------------------------------------------------------
__global__ __launch_bounds__(256, 2)
void bgemm_imma2_kernel(const int8_t* __restrict__ A,
                        const int8_t* __restrict__ B,
                        float* __restrict__ out)
{
    extern __shared__ char smem[];
    const uint32_t sb = smem_u32(smem);
    const int tid  = threadIdx.x;
    const int lane = tid & 31;
    const int w    = tid >> 5;
    const int wm   = w & 3;           // 4 m-warps: rows wm*32
    const int wn   = w >> 2;          // 2 n-warps: cols wn*64
    const int m0   = blockIdx.y * BM;
    const int n0   = blockIdx.x * BN;

    // ldmatrix lane addressing
    const int lrow = lane & 15;       // row within m16 / n-group pattern
    const int lhi  = (lane >> 4) * 16;        // 16B half select (A)
    const int brow = (lane >> 3) * 8 + (lane & 7);  // row within 32-row B group

    int acc[2][8][4];
    #pragma unroll
    for (int mt = 0; mt < 2; ++mt)
        #pragma unroll
        for (int nt = 0; nt < 8; ++nt)
            #pragma unroll
            for (int i = 0; i < 4; ++i) acc[mt][nt][i] = 0;

    // stage loader: 512 x 16B per operand, 2 per thread each.
    auto load_chunk = [&](int c, int s) {
        const uint32_t sa = sb + s * STG_SZ;
        const uint32_t sbB = sa + STG_A;
        #pragma unroll
        for (int i = 0; i < 2; ++i) {
            int id = i * 256 + tid;
            int row = id >> 2, seg = id & 3;
            cp16(sa + row * RS + seg * 16,
                 A + (size_t)(m0 + row) * INF + c * BK + seg * 16);
        }
        #pragma unroll
        for (int i = 0; i < 2; ++i) {
            int id = i * 256 + tid;
            int row = id >> 2, seg = id & 3;
            cp16(sbB + row * RS + seg * 16,
                 B + (size_t)(n0 + row) * INF + c * BK + seg * 16);
        }
        cp_commit();
    };

    load_chunk(0, 0);
    load_chunk(1, 1);

    for (int c = 0; c < KCHUNKS; ++c) {
        const int s = c % NSTG;
        if (c + 2 < KCHUNKS)      { load_chunk(c + 2, (c + 2) % NSTG); cp_wait<2>(); }
        else if (c + 1 < KCHUNKS) { cp_wait<1>(); }
        else                      { cp_wait<0>(); }
        __syncthreads();

        const uint32_t sa  = sb + s * STG_SZ;
        const uint32_t sbB = sa + STG_A;

        #pragma unroll
        for (int ks = 0; ks < 2; ++ks) {
            const int ko = ks * 32;
            uint32_t a[2][4];
            #pragma unroll
            for (int mt = 0; mt < 2; ++mt)
                ldm_x4(a[mt], sa + (wm * 32 + mt * 16 + lrow) * RS + lhi + ko);
            uint32_t b[8][2];
            #pragma unroll
            for (int g = 0; g < 2; ++g) {
                uint32_t blo[4], bhi[4];
                ldm_x4(blo, sbB + (wn * 64 + g * 32 + brow) * RS + ko);
                ldm_x4(bhi, sbB + (wn * 64 + g * 32 + brow) * RS + 16 + ko);
                #pragma unroll
                for (int j = 0; j < 4; ++j) {
                    b[g * 4 + j][0] = blo[j];
                    b[g * 4 + j][1] = bhi[j];
                }
            }
            #pragma unroll
            for (int mt = 0; mt < 2; ++mt)
                #pragma unroll
                for (int nt = 0; nt < 8; ++nt)
                    imma(acc[mt][nt], a[mt], b[nt]);
        }
        __syncthreads();
    }

    // Epilogue: d0,d1 -> (rg, tg*2..+1), d2,d3 -> (rg+8, ...)
    const int rg = lane >> 2;
    const int tg = lane & 3;
    #pragma unroll
    for (int mt = 0; mt < 2; ++mt) {
        const int r0 = m0 + wm * 32 + mt * 16 + rg;
        #pragma unroll
        for (int nt = 0; nt < 8; ++nt) {
            const int cc = n0 + wn * 64 + nt * 8 + tg * 2;
            float2 v0 = make_float2((float)acc[mt][nt][0], (float)acc[mt][nt][1]);
            float2 v1 = make_float2((float)acc[mt][nt][2], (float)acc[mt][nt][3]);
            *reinterpret_cast<float2*>(&out[(size_t)r0 * OUTF + cc])       = v0;
            *reinterpret_cast<float2*>(&out[(size_t)(r0 + 8) * OUTF + cc]) = v1;
        }
    }
}

// ---------------------------------------------------------------------------
extern "C" void kernel_launch(void* const* d_in, const int* in_sizes, int n_in,
                              void* d_out, int out_size)
{
    const float* x = (const float*)d_in[0];
    const float* W = (const float*)d_in[1];
    if (n_in >= 2 && in_sizes[0] == OUTF * INF && in_sizes[1] == BATCH * INF) {
        x = (const float*)d_in[1];
        W = (const float*)d_in[0];
    }
    float* out = (float*)d_out;

    int8_t* X8; int8_t* W8;
    cudaGetSymbolAddress((void**)&X8, g_X8);
    cudaGetSymbolAddress((void**)&W8, g_W8);

    conv_x8_kernel<<<(int)((size_t)BATCH * INF / 16 / 256), 256>>>(x, X8);
    conv_w8_kernel<<<(int)((size_t)OUTF * INF / 16 / 256), 256>>>(W, W8);

    cudaFuncSetAttribute(bgemm_imma2_kernel,
                         cudaFuncAttributeMaxDynamicSharedMemorySize, SM_TOTAL);
    dim3 grid(OUTF / BN, BATCH / BM);   // (32, 64)
    bgemm_imma2_kernel<<<grid, 256, SM_TOTAL>>>(X8, W8, out);
}

// round 14
// speedup vs baseline: 2.0345x; 2.0345x over previous
#include <cuda_runtime.h>
#include <stdint.h>

// QLinearLayerSign hybrid: popc binary GEMM (ALU pipe) + int8 mma.sync (tensor
// pipe) in ONE grid-heterogeneous kernel. Disjoint N split:
//   IMMA:  n in [0, 1280)     (tensor-capped, few issue slots)
//   POPC:  n in [1280, 4096)  (issue/ALU bound)
// Both exact: A in {0,1}, B/W in {-1,+1}, |acc| <= 4096.

#define BATCH 8192
#define INF   4096
#define OUTF  4096
#define KW    (INF / 32)

#define N_IMMA 1280

// IMMA side: CTA 128x64, warp tile 32x32, BK=64 bytes, 3-stage.
#define I_BM 128
#define I_BN 64
#define I_BK 64
#define I_KCH (INF / I_BK)          // 64
#define RS 80
#define I_STG ((I_BM + I_BN) * RS)  // 15360
#define I_NSTG 3

// POPC side: CTA 64x64, 4x4/thread, BKW=32 words (128B rows), 2-stage.
#define P_BM 64
#define P_BN 64
#define P_BKW 32
#define P_KCH (KW / P_BKW)          // 4
#define P_STGX (P_BM * 128)         // 8192
#define P_STG  (P_STGX + P_BN * 128)  // 16384

#define SM_TOTAL (I_NSTG * I_STG)   // 46080 (> 2*P_STG = 32768)

// grid composition: 6912 blocks = 27*256; bid%27<5 -> imma (1280), else popc (5632)
#define GRID_TOTAL 6912

__device__ int8_t   g_X8[(size_t)BATCH * INF];   // 32 MB
__device__ int8_t   g_W8[(size_t)OUTF * INF];    // 16 MB
__device__ uint32_t g_Xb[(size_t)BATCH * KW];    // 4 MB
__device__ uint32_t g_Wb[(size_t)OUTF * KW];     // 2 MB
__device__ int      g_Xr[BATCH];

__device__ __forceinline__ uint32_t smem_u32(const void* p) {
    uint32_t a;
    asm("{ .reg .u64 t; cvta.to.shared.u64 t, %1; cvt.u32.u64 %0, t; }" : "=r"(a) : "l"(p));
    return a;
}
__device__ __forceinline__ void cp16(uint32_t dst, const void* src) {
    asm volatile("cp.async.cg.shared.global [%0], [%1], 16;" :: "r"(dst), "l"(src));
}
__device__ __forceinline__ void cp_commit() {
    asm volatile("cp.async.commit_group;" ::: "memory");
}
template <int N> __device__ __forceinline__ void cp_wait() {
    asm volatile("cp.async.wait_group %0;" :: "n"(N) : "memory");
}
__device__ __forceinline__ void ldm_x4(uint32_t* r, uint32_t addr) {
    asm volatile("ldmatrix.sync.aligned.m8n8.x4.shared.b16 {%0,%1,%2,%3}, [%4];"
                 : "=r"(r[0]), "=r"(r[1]), "=r"(r[2]), "=r"(r[3]) : "r"(addr));
}
__device__ __forceinline__ void imma_op(int* d, const uint32_t* a, const uint32_t* b) {
    asm volatile(
        "mma.sync.aligned.m16n8k32.row.col.s32.s8.s8.s32 "
        "{%0,%1,%2,%3}, {%4,%5,%6,%7}, {%8,%9}, {%0,%1,%2,%3};"
        : "+r"(d[0]), "+r"(d[1]), "+r"(d[2]), "+r"(d[3])
        : "r"(a[0]), "r"(a[1]), "r"(a[2]), "r"(a[3]), "r"(b[0]), "r"(b[1]));
}

// ---------------------------------------------------------------------------
// Fused prologue: one pass over fp32 -> s8 bytes AND bitmask words.
// Each warp: 128 floats -> 128 s8 + 4 bit-words. mode 0: x (0/1), 1: W (1/-1).
// ---------------------------------------------------------------------------
template <int MODE>
__global__ __launch_bounds__(256) void fused_pack_kernel(
    const float* __restrict__ src, int8_t* __restrict__ d8,
    uint32_t* __restrict__ dbits)
{
    const int gw   = (int)(blockIdx.x * 8 + (threadIdx.x >> 5));
    const int lane = threadIdx.x & 31;
    float4 f = *reinterpret_cast<const float4*>(src + (size_t)gw * 128 + lane * 4);
    // s8 bytes
    uint32_t s8;
    if (MODE == 0)
        s8 = (f.x > 0.f ? 1u : 0u) | ((f.y > 0.f ? 1u : 0u) << 8) |
             ((f.z > 0.f ? 1u : 0u) << 16) | ((f.w > 0.f ? 1u : 0u) << 24);
    else
        s8 = (f.x > 0.f ? 1u : 0xFFu) | ((f.y > 0.f ? 1u : 0xFFu) << 8) |
             ((f.z > 0.f ? 1u : 0xFFu) << 16) | ((f.w > 0.f ? 1u : 0xFFu) << 24);
    reinterpret_cast<uint32_t*>(d8)[(size_t)gw * 32 + lane] = s8;
    // bitmask
    uint32_t nib = (f.x > 0.f ? 1u : 0u) | (f.y > 0.f ? 2u : 0u) |
                   (f.z > 0.f ? 4u : 0u) | (f.w > 0.f ? 8u : 0u);
    uint32_t v = nib << ((lane & 7) * 4);
    v |= __shfl_xor_sync(0xFFFFFFFFu, v, 1);
    v |= __shfl_xor_sync(0xFFFFFFFFu, v, 2);
    v |= __shfl_xor_sync(0xFFFFFFFFu, v, 4);
    uint32_t w0 = __shfl_sync(0xFFFFFFFFu, v, 0);
    uint32_t w1 = __shfl_sync(0xFFFFFFFFu, v, 8);
    uint32_t w2 = __shfl_sync(0xFFFFFFFFu, v, 16);
    uint32_t w3 = __shfl_sync(0xFFFFFFFFu, v, 24);
    if (lane == 0)
        *reinterpret_cast<uint4*>(dbits + (size_t)gw * 4) = make_uint4(w0, w1, w2, w3);
}

__global__ __launch_bounds__(256) void row_popc_kernel(
    const uint32_t* __restrict__ Xb, int* __restrict__ Xr, int rows)
{
    int row  = (int)(blockIdx.x * 8 + (threadIdx.x >> 5));
    int lane = threadIdx.x & 31;
    if (row >= rows) return;
    const uint32_t* p = Xb + (size_t)row * KW;
    int s = 0;
    #pragma unroll
    for (int i = 0; i < KW / 32; i++) s += __popc(p[lane + i * 32]);
    #pragma unroll
    for (int o = 16; o; o >>= 1) s += __shfl_xor_sync(0xFFFFFFFFu, s, o);
    if (lane == 0) Xr[row] = s;
}

// ---------------------------------------------------------------------------
// Hybrid kernel.
// ---------------------------------------------------------------------------
__global__ __launch_bounds__(256, 3)
void hybrid_kernel(const int8_t*   __restrict__ A8,
                   const int8_t*   __restrict__ B8,
                   const uint32_t* __restrict__ Xb,
                   const uint32_t* __restrict__ Wb,
                   const int*      __restrict__ Xr,
                   float*          __restrict__ out)
{
    extern __shared__ char smem[];
    const uint32_t sb = smem_u32(smem);
    const int tid  = threadIdx.x;
    const int bid  = blockIdx.x;
    const int slot = bid % 27;

    if (slot < 5) {
        // ================= IMMA path: n in [0, N_IMMA) =================
        const int i     = (bid / 27) * 5 + slot;       // 0..1279
        const int m0    = (i / 20) * I_BM;
        const int n0    = (i % 20) * I_BN;
        const int lane  = tid & 31;
        const int w     = tid >> 5;
        const int wm    = w & 3;                       // rows wm*32
        const int wn    = w >> 2;                      // cols wn*32
        const int lrow  = lane & 15;
        const int lhi   = (lane >> 4) * 16;

        int acc[2][4][4];
        #pragma unroll
        for (int mt = 0; mt < 2; ++mt)
            #pragma unroll
            for (int nt = 0; nt < 4; ++nt)
                #pragma unroll
                for (int k = 0; k < 4; ++k) acc[mt][nt][k] = 0;

        auto load_chunk = [&](int c, int s) {
            const uint32_t sa  = sb + s * I_STG;
            const uint32_t sbB = sa + I_BM * RS;
            #pragma unroll
            for (int it = 0; it < 2; ++it) {          // A: 512 x 16B
                int id = it * 256 + tid;
                int row = id >> 2, seg = id & 3;
                cp16(sa + row * RS + seg * 16,
                     A8 + (size_t)(m0 + row) * INF + c * I_BK + seg * 16);
            }
            {                                          // B: 256 x 16B
                int row = tid >> 2, seg = tid & 3;
                cp16(sbB + row * RS + seg * 16,
                     B8 + (size_t)(n0 + row) * INF + c * I_BK + seg * 16);
            }
            cp_commit();
        };

        load_chunk(0, 0);
        load_chunk(1, 1);

        for (int c = 0; c < I_KCH; ++c) {
            const int s = c % I_NSTG;
            if (c + 2 < I_KCH)      { load_chunk(c + 2, (c + 2) % I_NSTG); cp_wait<2>(); }
            else if (c + 1 < I_KCH) { cp_wait<1>(); }
            else                    { cp_wait<0>(); }
            __syncthreads();

            const uint32_t sa  = sb + s * I_STG;
            const uint32_t sbB = sa + I_BM * RS;

            #pragma unroll
            for (int ks = 0; ks < 2; ++ks) {
                const int ko = ks * 32;
                uint32_t a[2][4];
                #pragma unroll
                for (int mt = 0; mt < 2; ++mt)
                    ldm_x4(a[mt], sa + (wm * 32 + mt * 16 + lrow) * RS + lhi + ko);
                uint32_t blo[4], bhi[4];
                ldm_x4(blo, sbB + (wn * 32 + lane) * RS + ko);
                ldm_x4(bhi, sbB + (wn * 32 + lane) * RS + 16 + ko);
                #pragma unroll
                for (int mt = 0; mt < 2; ++mt)
                    #pragma unroll
                    for (int nt = 0; nt < 4; ++nt) {
                        uint32_t b2[2] = { blo[nt], bhi[nt] };
                        imma_op(acc[mt][nt], a[mt], b2);
                    }
            }
            __syncthreads();
        }

        const int rg = lane >> 2, tg = lane & 3;
        #pragma unroll
        for (int mt = 0; mt < 2; ++mt) {
            const int r0 = m0 + wm * 32 + mt * 16 + rg;
            #pragma unroll
            for (int nt = 0; nt < 4; ++nt) {
                const int cc = n0 + wn * 32 + nt * 8 + tg * 2;
                float2 v0 = make_float2((float)acc[mt][nt][0], (float)acc[mt][nt][1]);
                float2 v1 = make_float2((float)acc[mt][nt][2], (float)acc[mt][nt][3]);
                *reinterpret_cast<float2*>(&out[(size_t)r0 * OUTF + cc])       = v0;
                *reinterpret_cast<float2*>(&out[(size_t)(r0 + 8) * OUTF + cc]) = v1;
            }
        }
    } else {
        // ================= POPC path: n in [N_IMMA, 4096) =================
        const int j  = (bid / 27) * 22 + (slot - 5);   // 0..5631
        const int m0 = (j / 44) * P_BM;
        const int n0 = N_IMMA + (j % 44) * P_BN;
        const int tx = tid & 15;
        const int ty = tid >> 4;
        const int sA = (ty >> 1) & 7;
        const int sB = (tx >> 1) & 7;

        auto load_chunk = [&](int c, int s) {
            const uint32_t bx = sb + s * P_STG;
            const uint32_t bw = bx + P_STGX;
            #pragma unroll
            for (int it = 0; it < 2; ++it) {
                int id  = it * 256 + tid;
                int row = id >> 3, seg = id & 7;
                int sw  = (seg ^ ((row >> 3) & 7)) * 16;
                cp16(bx + row * 128 + sw, Xb + (size_t)(m0 + row) * KW + c * P_BKW + seg * 4);
            }
            #pragma unroll
            for (int it = 0; it < 2; ++it) {
                int id  = it * 256 + tid;
                int row = id >> 3, seg = id & 7;
                int sw  = (seg ^ ((row >> 3) & 7)) * 16;
                cp16(bw + row * 128 + sw, Wb + (size_t)(n0 + row) * KW + c * P_BKW + seg * 4);
            }
            cp_commit();
        };

        int acc[4][4];
        #pragma unroll
        for (int a = 0; a < 4; ++a)
            #pragma unroll
            for (int b = 0; b < 4; ++b) acc[a][b] = 0;

        load_chunk(0, 0);

        for (int c = 0; c < P_KCH; ++c) {
            const int s = c & 1;
            if (c + 1 < P_KCH) { load_chunk(c + 1, s ^ 1); cp_wait<1>(); }
            else               { cp_wait<0>(); }
            __syncthreads();

            const char* xs = smem + s * P_STG + (ty * 4) * 128;
            const char* ws = smem + s * P_STG + P_STGX + (tx * 4) * 128;

            #pragma unroll
            for (int k4 = 0; k4 < 8; ++k4) {
                const int ca = (k4 ^ sA) * 16;
                const int cb = (k4 ^ sB) * 16;
                uint4 a0 = *reinterpret_cast<const uint4*>(xs + 0 * 128 + ca);
                uint4 a1 = *reinterpret_cast<const uint4*>(xs + 1 * 128 + ca);
                uint4 a2 = *reinterpret_cast<const uint4*>(xs + 2 * 128 + ca);
                uint4 a3 = *reinterpret_cast<const uint4*>(xs + 3 * 128 + ca);
                #pragma unroll
                for (int nt = 0; nt < 4; ++nt) {
                    uint4 b = *reinterpret_cast<const uint4*>(ws + nt * 128 + cb);
                    acc[0][nt] += __popc(a0.x & b.x) + __popc(a0.y & b.y)
                                + __popc(a0.z & b.z) + __popc(a0.w & b.w);
                    acc[1][nt] += __popc(a1.x & b.x) + __popc(a1.y & b.y)
                                + __popc(a1.z & b.z) + __popc(a1.w & b.w);
                    acc[2][nt] += __popc(a2.x & b.x) + __popc(a2.y & b.y)
                                + __popc(a2.z & b.z) + __popc(a2.w & b.w);
                    acc[3][nt] += __popc(a3.x & b.x) + __popc(a3.y & b.y)
                                + __popc(a3.z & b.z) + __popc(a3.w & b.w);
                }
            }
            __syncthreads();
        }

        #pragma unroll
        for (int mt = 0; mt < 4; ++mt) {
            const int m = m0 + ty * 4 + mt;
            const int R = Xr[m];
            float4 v;
            v.x = (float)(2 * acc[mt][0] - R);
            v.y = (float)(2 * acc[mt][1] - R);
            v.z = (float)(2 * acc[mt][2] - R);
            v.w = (float)(2 * acc[mt][3] - R);
            *reinterpret_cast<float4*>(&out[(size_t)m * OUTF + n0 + tx * 4]) = v;
        }
    }
}

// ---------------------------------------------------------------------------
extern "C" void kernel_launch(void* const* d_in, const int* in_sizes, int n_in,
                              void* d_out, int out_size)
{
    const float* x = (const float*)d_in[0];
    const float* W = (const float*)d_in[1];
    if (n_in >= 2 && in_sizes[0] == OUTF * INF && in_sizes[1] == BATCH * INF) {
        x = (const float*)d_in[1];
        W = (const float*)d_in[0];
    }
    float* out = (float*)d_out;

    int8_t* X8; int8_t* W8; uint32_t* Xb; uint32_t* Wb; int* Xr;
    cudaGetSymbolAddress((void**)&X8, g_X8);
    cudaGetSymbolAddress((void**)&W8, g_W8);
    cudaGetSymbolAddress((void**)&Xb, g_Xb);
    cudaGetSymbolAddress((void**)&Wb, g_Wb);
    cudaGetSymbolAddress((void**)&Xr, g_Xr);

    fused_pack_kernel<0><<<(int)((size_t)BATCH * INF / 128 / 8), 256>>>(x, X8, Xb);
    fused_pack_kernel<1><<<(int)((size_t)OUTF * INF / 128 / 8), 256>>>(W, W8, Wb);
    row_popc_kernel<<<BATCH / 8, 256>>>(Xb, Xr, BATCH);

    cudaFuncSetAttribute(hybrid_kernel,
                         cudaFuncAttributeMaxDynamicSharedMemorySize, SM_TOTAL);
    hybrid_kernel<<<GRID_TOTAL, 256, SM_TOTAL>>>(X8, W8, Xb, Wb, Xr, out);
}

// round 15
// speedup vs baseline: 2.0474x; 1.0063x over previous
#include <cuda_runtime.h>
#include <stdint.h>

// QLinearLayerSign hybrid v2: popc (ALU pipe) + int8 mma.sync (tensor pipe),
// one grid-heterogeneous kernel, 4 CTAs/SM (occupancy-first).
//   IMMA:  n in [0, 1280)     POPC: n in [1280, 4096)
// Both exact: A in {0,1}, B/W in {-1,+1}, |acc| <= 4096.

#define BATCH 8192
#define INF   4096
#define OUTF  4096
#define KW    (INF / 32)

#define N_IMMA 1280

// IMMA side: CTA 128x64, warp tile 32x32, BK=64 bytes, 2-stage.
#define I_BM 128
#define I_BN 64
#define I_BK 64
#define I_KCH (INF / I_BK)          // 64
#define RS 80
#define I_STG ((I_BM + I_BN) * RS)  // 15360
// POPC side: CTA 64x64, 4x4/thread, BKW=32 words, 2-stage.
#define P_BM 64
#define P_BN 64
#define P_BKW 32
#define P_KCH (KW / P_BKW)          // 4
#define P_STGX (P_BM * 128)         // 8192
#define P_STG  (P_STGX + P_BN * 128)  // 16384

#define SM_TOTAL (2 * P_STG)        // 32768 (>= 2*I_STG = 30720)

#define GRID_TOTAL 6912             // 27*256; slot<5 -> imma(1280), else popc(5632)

__device__ int8_t   g_X8[(size_t)BATCH * INF];
__device__ int8_t   g_W8[(size_t)OUTF * INF];
__device__ uint32_t g_Xb[(size_t)BATCH * KW];
__device__ uint32_t g_Wb[(size_t)OUTF * KW];
__device__ int      g_Xr[BATCH];

__device__ __forceinline__ uint32_t smem_u32(const void* p) {
    uint32_t a;
    asm("{ .reg .u64 t; cvta.to.shared.u64 t, %1; cvt.u32.u64 %0, t; }" : "=r"(a) : "l"(p));
    return a;
}
__device__ __forceinline__ void cp16(uint32_t dst, const void* src) {
    asm volatile("cp.async.cg.shared.global [%0], [%1], 16;" :: "r"(dst), "l"(src));
}
__device__ __forceinline__ void cp_commit() {
    asm volatile("cp.async.commit_group;" ::: "memory");
}
template <int N> __device__ __forceinline__ void cp_wait() {
    asm volatile("cp.async.wait_group %0;" :: "n"(N) : "memory");
}
__device__ __forceinline__ void ldm_x4(uint32_t* r, uint32_t addr) {
    asm volatile("ldmatrix.sync.aligned.m8n8.x4.shared.b16 {%0,%1,%2,%3}, [%4];"
                 : "=r"(r[0]), "=r"(r[1]), "=r"(r[2]), "=r"(r[3]) : "r"(addr));
}
__device__ __forceinline__ void imma_op(int* d, const uint32_t* a, const uint32_t* b) {
    asm volatile(
        "mma.sync.aligned.m16n8k32.row.col.s32.s8.s8.s32 "
        "{%0,%1,%2,%3}, {%4,%5,%6,%7}, {%8,%9}, {%0,%1,%2,%3};"
        : "+r"(d[0]), "+r"(d[1]), "+r"(d[2]), "+r"(d[3])
        : "r"(a[0]), "r"(a[1]), "r"(a[2]), "r"(a[3]), "r"(b[0]), "r"(b[1]));
}

// ---------------------------------------------------------------------------
// Fused prologue: fp32 -> s8 bytes AND bitmask words in one pass.
// ---------------------------------------------------------------------------
template <int MODE>
__global__ __launch_bounds__(256) void fused_pack_kernel(
    const float* __restrict__ src, int8_t* __restrict__ d8,
    uint32_t* __restrict__ dbits)
{
    const int gw   = (int)(blockIdx.x * 8 + (threadIdx.x >> 5));
    const int lane = threadIdx.x & 31;
    float4 f = *reinterpret_cast<const float4*>(src + (size_t)gw * 128 + lane * 4);
    uint32_t s8;
    if (MODE == 0)
        s8 = (f.x > 0.f ? 1u : 0u) | ((f.y > 0.f ? 1u : 0u) << 8) |
             ((f.z > 0.f ? 1u : 0u) << 16) | ((f.w > 0.f ? 1u : 0u) << 24);
    else
        s8 = (f.x > 0.f ? 1u : 0xFFu) | ((f.y > 0.f ? 1u : 0xFFu) << 8) |
             ((f.z > 0.f ? 1u : 0xFFu) << 16) | ((f.w > 0.f ? 1u : 0xFFu) << 24);
    reinterpret_cast<uint32_t*>(d8)[(size_t)gw * 32 + lane] = s8;
    uint32_t nib = (f.x > 0.f ? 1u : 0u) | (f.y > 0.f ? 2u : 0u) |
                   (f.z > 0.f ? 4u : 0u) | (f.w > 0.f ? 8u : 0u);
    uint32_t v = nib << ((lane & 7) * 4);
    v |= __shfl_xor_sync(0xFFFFFFFFu, v, 1);
    v |= __shfl_xor_sync(0xFFFFFFFFu, v, 2);
    v |= __shfl_xor_sync(0xFFFFFFFFu, v, 4);
    uint32_t w0 = __shfl_sync(0xFFFFFFFFu, v, 0);
    uint32_t w1 = __shfl_sync(0xFFFFFFFFu, v, 8);
    uint32_t w2 = __shfl_sync(0xFFFFFFFFu, v, 16);
    uint32_t w3 = __shfl_sync(0xFFFFFFFFu, v, 24);
    if (lane == 0)
        *reinterpret_cast<uint4*>(dbits + (size_t)gw * 4) = make_uint4(w0, w1, w2, w3);
}

__global__ __launch_bounds__(256) void row_popc_kernel(
    const uint32_t* __restrict__ Xb, int* __restrict__ Xr, int rows)
{
    int row  = (int)(blockIdx.x * 8 + (threadIdx.x >> 5));
    int lane = threadIdx.x & 31;
    if (row >= rows) return;
    const uint32_t* p = Xb + (size_t)row * KW;
    int s = 0;
    #pragma unroll
    for (int i = 0; i < KW / 32; i++) s += __popc(p[lane + i * 32]);
    #pragma unroll
    for (int o = 16; o; o >>= 1) s += __shfl_xor_sync(0xFFFFFFFFu, s, o);
    if (lane == 0) Xr[row] = s;
}

// ---------------------------------------------------------------------------
// Hybrid kernel v2 (4 CTAs/SM).
// ---------------------------------------------------------------------------
__global__ __launch_bounds__(256, 4)
void hybrid_kernel(const int8_t*   __restrict__ A8,
                   const int8_t*   __restrict__ B8,
                   const uint32_t* __restrict__ Xb,
                   const uint32_t* __restrict__ Wb,
                   const int*      __restrict__ Xr,
                   float*          __restrict__ out)
{
    extern __shared__ char smem[];
    const uint32_t sb = smem_u32(smem);
    const int tid  = threadIdx.x;
    const int bid  = blockIdx.x;
    const int slot = bid % 27;

    if (slot < 5) {
        // ================= IMMA path: n in [0, N_IMMA), 2-stage =================
        const int i     = (bid / 27) * 5 + slot;       // 0..1279
        const int m0    = (i / 20) * I_BM;
        const int n0    = (i % 20) * I_BN;
        const int lane  = tid & 31;
        const int w     = tid >> 5;
        const int wm    = w & 3;
        const int wn    = w >> 2;
        const int lrow  = lane & 15;
        const int lhi   = (lane >> 4) * 16;

        int acc[2][4][4];
        #pragma unroll
        for (int mt = 0; mt < 2; ++mt)
            #pragma unroll
            for (int nt = 0; nt < 4; ++nt)
                #pragma unroll
                for (int k = 0; k < 4; ++k) acc[mt][nt][k] = 0;

        auto load_chunk = [&](int c, int s) {
            const uint32_t sa  = sb + s * I_STG;
            const uint32_t sbB = sa + I_BM * RS;
            #pragma unroll
            for (int it = 0; it < 2; ++it) {
                int id = it * 256 + tid;
                int row = id >> 2, seg = id & 3;
                cp16(sa + row * RS + seg * 16,
                     A8 + (size_t)(m0 + row) * INF + c * I_BK + seg * 16);
            }
            {
                int row = tid >> 2, seg = tid & 3;
                cp16(sbB + row * RS + seg * 16,
                     B8 + (size_t)(n0 + row) * INF + c * I_BK + seg * 16);
            }
            cp_commit();
        };

        load_chunk(0, 0);

        for (int c = 0; c < I_KCH; ++c) {
            const int s = c & 1;
            if (c + 1 < I_KCH) { load_chunk(c + 1, s ^ 1); cp_wait<1>(); }
            else               { cp_wait<0>(); }
            __syncthreads();

            const uint32_t sa  = sb + s * I_STG;
            const uint32_t sbB = sa + I_BM * RS;

            #pragma unroll
            for (int ks = 0; ks < 2; ++ks) {
                const int ko = ks * 32;
                uint32_t a[2][4];
                #pragma unroll
                for (int mt = 0; mt < 2; ++mt)
                    ldm_x4(a[mt], sa + (wm * 32 + mt * 16 + lrow) * RS + lhi + ko);
                uint32_t blo[4], bhi[4];
                ldm_x4(blo, sbB + (wn * 32 + lane) * RS + ko);
                ldm_x4(bhi, sbB + (wn * 32 + lane) * RS + 16 + ko);
                #pragma unroll
                for (int mt = 0; mt < 2; ++mt)
                    #pragma unroll
                    for (int nt = 0; nt < 4; ++nt) {
                        uint32_t b2[2] = { blo[nt], bhi[nt] };
                        imma_op(acc[mt][nt], a[mt], b2);
                    }
            }
            __syncthreads();
        }

        const int rg = lane >> 2, tg = lane & 3;
        #pragma unroll
        for (int mt = 0; mt < 2; ++mt) {
            const int r0 = m0 + wm * 32 + mt * 16 + rg;
            #pragma unroll
            for (int nt = 0; nt < 4; ++nt) {
                const int cc = n0 + wn * 32 + nt * 8 + tg * 2;
                float2 v0 = make_float2((float)acc[mt][nt][0], (float)acc[mt][nt][1]);
                float2 v1 = make_float2((float)acc[mt][nt][2], (float)acc[mt][nt][3]);
                *reinterpret_cast<float2*>(&out[(size_t)r0 * OUTF + cc])       = v0;
                *reinterpret_cast<float2*>(&out[(size_t)(r0 + 8) * OUTF + cc]) = v1;
            }
        }
    } else {
        // ================= POPC path: n in [N_IMMA, 4096) =================
        const int j  = (bid / 27) * 22 + (slot - 5);   // 0..5631
        const int m0 = (j / 44) * P_BM;
        const int n0 = N_IMMA + (j % 44) * P_BN;
        const int tx = tid & 15;
        const int ty = tid >> 4;
        const int sA = (ty >> 1) & 7;
        const int sB = (tx >> 1) & 7;

        auto load_chunk = [&](int c, int s) {
            const uint32_t bx = sb + s * P_STG;
            const uint32_t bw = bx + P_STGX;
            #pragma unroll
            for (int it = 0; it < 2; ++it) {
                int id  = it * 256 + tid;
                int row = id >> 3, seg = id & 7;
                int sw  = (seg ^ ((row >> 3) & 7)) * 16;
                cp16(bx + row * 128 + sw, Xb + (size_t)(m0 + row) * KW + c * P_BKW + seg * 4);
            }
            #pragma unroll
            for (int it = 0; it < 2; ++it) {
                int id  = it * 256 + tid;
                int row = id >> 3, seg = id & 7;
                int sw  = (seg ^ ((row >> 3) & 7)) * 16;
                cp16(bw + row * 128 + sw, Wb + (size_t)(n0 + row) * KW + c * P_BKW + seg * 4);
            }
            cp_commit();
        };

        int acc[4][4];
        #pragma unroll
        for (int a = 0; a < 4; ++a)
            #pragma unroll
            for (int b = 0; b < 4; ++b) acc[a][b] = 0;

        load_chunk(0, 0);

        for (int c = 0; c < P_KCH; ++c) {
            const int s = c & 1;
            if (c + 1 < P_KCH) { load_chunk(c + 1, s ^ 1); cp_wait<1>(); }
            else               { cp_wait<0>(); }
            __syncthreads();

            const char* xs = smem + s * P_STG + (ty * 4) * 128;
            const char* ws = smem + s * P_STG + P_STGX + (tx * 4) * 128;

            #pragma unroll
            for (int k4 = 0; k4 < 8; ++k4) {
                const int ca = (k4 ^ sA) * 16;
                const int cb = (k4 ^ sB) * 16;
                uint4 a0 = *reinterpret_cast<const uint4*>(xs + 0 * 128 + ca);
                uint4 a1 = *reinterpret_cast<const uint4*>(xs + 1 * 128 + ca);
                uint4 a2 = *reinterpret_cast<const uint4*>(xs + 2 * 128 + ca);
                uint4 a3 = *reinterpret_cast<const uint4*>(xs + 3 * 128 + ca);
                #pragma unroll
                for (int nt = 0; nt < 4; ++nt) {
                    uint4 b = *reinterpret_cast<const uint4*>(ws + nt * 128 + cb);
                    acc[0][nt] += __popc(a0.x & b.x) + __popc(a0.y & b.y)
                                + __popc(a0.z & b.z) + __popc(a0.w & b.w);
                    acc[1][nt] += __popc(a1.x & b.x) + __popc(a1.y & b.y)
                                + __popc(a1.z & b.z) + __popc(a1.w & b.w);
                    acc[2][nt] += __popc(a2.x & b.x) + __popc(a2.y & b.y)
                                + __popc(a2.z & b.z) + __popc(a2.w & b.w);
                    acc[3][nt] += __popc(a3.x & b.x) + __popc(a3.y & b.y)
                                + __popc(a3.z & b.z) + __popc(a3.w & b.w);
                }
            }
            __syncthreads();
        }

        #pragma unroll
        for (int mt = 0; mt < 4; ++mt) {
            const int m = m0 + ty * 4 + mt;
            const int R = Xr[m];
            float4 v;
            v.x = (float)(2 * acc[mt][0] - R);
            v.y = (float)(2 * acc[mt][1] - R);
            v.z = (float)(2 * acc[mt][2] - R);
            v.w = (float)(2 * acc[mt][3] - R);
            *reinterpret_cast<float4*>(&out[(size_t)m * OUTF + n0 + tx * 4]) = v;
        }
    }
}

// ---------------------------------------------------------------------------
extern "C" void kernel_launch(void* const* d_in, const int* in_sizes, int n_in,
                              void* d_out, int out_size)
{
    const float* x = (const float*)d_in[0];
    const float* W = (const float*)d_in[1];
    if (n_in >= 2 && in_sizes[0] == OUTF * INF && in_sizes[1] == BATCH * INF) {
        x = (const float*)d_in[1];
        W = (const float*)d_in[0];
    }
    float* out = (float*)d_out;

    int8_t* X8; int8_t* W8; uint32_t* Xb; uint32_t* Wb; int* Xr;
    cudaGetSymbolAddress((void**)&X8, g_X8);
    cudaGetSymbolAddress((void**)&W8, g_W8);
    cudaGetSymbolAddress((void**)&Xb, g_Xb);
    cudaGetSymbolAddress((void**)&Wb, g_Wb);
    cudaGetSymbolAddress((void**)&Xr, g_Xr);

    fused_pack_kernel<0><<<(int)((size_t)BATCH * INF / 128 / 8), 256>>>(x, X8, Xb);
    fused_pack_kernel<1><<<(int)((size_t)OUTF * INF / 128 / 8), 256>>>(W, W8, Wb);
    row_popc_kernel<<<BATCH / 8, 256>>>(Xb, Xr, BATCH);

    cudaFuncSetAttribute(hybrid_kernel,
                         cudaFuncAttributeMaxDynamicSharedMemorySize, SM_TOTAL);
    hybrid_kernel<<<GRID_TOTAL, 256, SM_TOTAL>>>(X8, W8, Xb, Wb, Xr, out);
}